// round 1
// baseline (speedup 1.0000x reference)
#include <cuda_runtime.h>

// Problem shape (fixed by the reference)
#define B_  8
#define T_  4096
#define D_  1024
#define CH_ 64          // chunks along T
#define L_  (T_ / CH_)  // 64 steps per chunk
#define TPB 256         // each thread owns 4 contiguous d's -> covers D=1024

// Scratch: per-chunk aggregates and carries.  8*64*1024 floats = 2 MiB each.
__device__ float g_A[B_ * CH_ * D_];
__device__ float g_U[B_ * CH_ * D_];
__device__ float g_C[B_ * CH_ * D_];

__device__ __forceinline__ float4 f4_fma(float4 a, float4 x, float4 u) {
    float4 r;
    r.x = fmaf(a.x, x.x, u.x);
    r.y = fmaf(a.y, x.y, u.y);
    r.z = fmaf(a.z, x.z, u.z);
    r.w = fmaf(a.w, x.w, u.w);
    return r;
}
__device__ __forceinline__ float4 f4_mul(float4 a, float4 b) {
    float4 r; r.x = a.x*b.x; r.y = a.y*b.y; r.z = a.z*b.z; r.w = a.w*b.w; return r;
}

// Pass 1: per-chunk reduce.  A = prod(a over chunk), U = scan(u;a) with zero init.
__global__ void k_reduce(const float* __restrict__ a,
                         const float* __restrict__ u,
                         const float* __restrict__ x0) {
    const int c = blockIdx.x;
    const int b = blockIdx.y;
    const int d = threadIdx.x * 4;

    const long base = (((long)b * T_ + (long)c * L_) * D_ + d) / 4;  // in float4 units
    const float4* __restrict__ ap = reinterpret_cast<const float4*>(a) + base;
    const float4* __restrict__ up = reinterpret_cast<const float4*>(u) + base;

    float4 A = make_float4(1.f, 1.f, 1.f, 1.f);
    float4 U = make_float4(0.f, 0.f, 0.f, 0.f);

    float4 x0v = make_float4(0.f, 0.f, 0.f, 0.f);
    if (c == 0) x0v = reinterpret_cast<const float4*>(x0)[(b * D_ + d) / 4];

    #pragma unroll 4
    for (int t = 0; t < L_; ++t) {
        float4 av = ap[(long)t * (D_ / 4)];
        float4 uv = up[(long)t * (D_ / 4)];
        if (c == 0 && t == 0) uv = f4_fma(av, x0v, uv);  // fold x0 into u at t=0
        U = f4_fma(av, U, uv);
        A = f4_mul(A, av);
    }

    const int sidx = ((b * CH_ + c) * D_ + d) / 4;
    reinterpret_cast<float4*>(g_A)[sidx] = A;
    reinterpret_cast<float4*>(g_U)[sidx] = U;
}

// Pass 2: serial scan over chunk summaries -> carry-in for each chunk.
__global__ void k_scan() {
    const int b = blockIdx.x;
    const int d = threadIdx.x * 4;

    float4 x = make_float4(0.f, 0.f, 0.f, 0.f);
    #pragma unroll 1
    for (int c = 0; c < CH_; ++c) {
        const int sidx = ((b * CH_ + c) * D_ + d) / 4;
        reinterpret_cast<float4*>(g_C)[sidx] = x;  // carry-in = inclusive of previous chunk
        float4 A = reinterpret_cast<const float4*>(g_A)[sidx];
        float4 U = reinterpret_cast<const float4*>(g_U)[sidx];
        x = f4_fma(A, x, U);
    }
}

// Pass 3: re-stream a,u with the correct carry and write the output.
__global__ void k_apply(const float* __restrict__ a,
                        const float* __restrict__ u,
                        const float* __restrict__ x0,
                        float* __restrict__ out) {
    const int c = blockIdx.x;
    const int b = blockIdx.y;
    const int d = threadIdx.x * 4;

    const long base = (((long)b * T_ + (long)c * L_) * D_ + d) / 4;
    const float4* __restrict__ ap = reinterpret_cast<const float4*>(a) + base;
    const float4* __restrict__ up = reinterpret_cast<const float4*>(u) + base;
    float4* __restrict__ op = reinterpret_cast<float4*>(out) + base;

    float4 x = reinterpret_cast<const float4*>(g_C)[((b * CH_ + c) * D_ + d) / 4];

    float4 x0v = make_float4(0.f, 0.f, 0.f, 0.f);
    if (c == 0) x0v = reinterpret_cast<const float4*>(x0)[(b * D_ + d) / 4];

    #pragma unroll 4
    for (int t = 0; t < L_; ++t) {
        float4 av = ap[(long)t * (D_ / 4)];
        float4 uv = up[(long)t * (D_ / 4)];
        if (c == 0 && t == 0) uv = f4_fma(av, x0v, uv);
        x = f4_fma(av, x, uv);
        op[(long)t * (D_ / 4)] = x;
    }
}

extern "C" void kernel_launch(void* const* d_in, const int* in_sizes, int n_in,
                              void* d_out, int out_size) {
    const float* x0 = (const float*)d_in[0];
    const float* a  = (const float*)d_in[1];
    const float* u  = (const float*)d_in[2];
    float* out = (float*)d_out;

    dim3 grid(CH_, B_);
    k_reduce<<<grid, TPB>>>(a, u, x0);
    k_scan<<<B_, TPB>>>();
    k_apply<<<grid, TPB>>>(a, u, x0, out);
}